// round 8
// baseline (speedup 1.0000x reference)
#include <cuda_runtime.h>

namespace {

constexpr int Bb  = 2;
constexpr int Nn  = 512;
constexpr int Mm  = 256;
constexpr int Dd  = 32;
constexpr int Tt  = 128;
constexpr int ORD = 2;
constexpr int CC  = 96;   // (ORD+1)*Dd
constexpr int CO  = 64;

constexpr int BM   = 128;
constexpr int BK   = 32;
constexpr int BDIM = 256;
constexpr int NCH  = Nn / BK;   // 16

typedef unsigned long long u64;

struct Smem {
    union {
        float adjt[2][ORD][BK][BM];   // 64 KB, main loop (double-buffered)
        float agg[BM][CC];            // 48 KB, epilogue/MLP
    } u;
    u64   gd[2][BK][Dd];              // (g,g) duplicated pairs: 16 KB
    u64   mskd[Nn];                   // (1-mask,1-mask) pairs:   4 KB
    float Wt[CC][CO];                 // W transposed:            24 KB
};
constexpr int SMEM_BYTES = (int)sizeof(Smem);  // 110592 B -> 2 CTAs/SM

__device__ __forceinline__ void ffma2(u64& d, u64 a, u64 b) {
    asm("fma.rn.f32x2 %0, %1, %2, %0;" : "+l"(d) : "l"(a), "l"(b));
}
__device__ __forceinline__ u64 dup2(float v) {
    u64 r; asm("mov.b64 %0, {%1, %1};" : "=l"(r) : "f"(v)); return r;
}
__device__ __forceinline__ float lo32(u64 v) { return __uint_as_float((unsigned)v); }
__device__ __forceinline__ float hi32(u64 v) { return __uint_as_float((unsigned)(v >> 32)); }

__global__ void __launch_bounds__(BDIM, 2)
graph_agg_kernel(const float* __restrict__ fc,    // [B,N,D,T]
                 const float* __restrict__ ft,    // [B,M,D,T]
                 const float* __restrict__ adj,   // [B,ORD,M,N]
                 const float* __restrict__ mask,  // [B,T,N]
                 const float* __restrict__ Wm,    // [CO,CC]
                 const float* __restrict__ bm,    // [CO]
                 float* __restrict__ out)         // [B,M,CO,T]
{
    extern __shared__ char smraw[];
    Smem& S = *reinterpret_cast<Smem*>(smraw);

    const int t   = blockIdx.x;
    const int mt  = blockIdx.y;
    const int b   = blockIdx.z;
    const int tid = threadIdx.x;

    // ---------------- prologue: Wt, mskd ----------------
    for (int i = tid; i < CO * CC; i += BDIM) {
        int o = i / CC, c = i % CC;
        S.Wt[c][o] = Wm[i];
    }
    {
        const float* maskp = mask + (b * Tt + t) * Nn;
        #pragma unroll
        for (int r = 0; r < Nn / BDIM; ++r) {
            int n = tid + r * BDIM;
            S.mskd[n] = dup2(1.0f - maskp[n]);
        }
    }
    __syncthreads();

    // compute-role ids
    const int kk = tid >> 7;          // order (0/1)
    const int mg = (tid >> 3) & 15;   // m-group: 8 rows (4 m-pairs)
    const int dg = tid & 7;           // d-group: 4 cols

    // loader ids
    const int kL = tid >> 7;
    const int mL = tid & 127;
    const float* adjp = adj + (size_t)((b * ORD + kL) * Mm + mt * BM + mL) * Nn;
    const int dl = tid & 31;          // d lane for gd producer
    const int ng = tid >> 5;          // n sub-row (8 rows/round)
    const float* fcb = fc + ((size_t)(b * Nn) * Dd + dl) * Tt + t;

    u64 acc[4][4];                    // [m-pair][d], each = (m_even, m_odd)
    u64 dacc[4];
    #pragma unroll
    for (int i = 0; i < 4; ++i) {
        dacc[i] = 0ull;
        #pragma unroll
        for (int j = 0; j < 4; ++j) acc[i][j] = 0ull;
    }

    // ---------------- main loop: raw = adj @ g, denom = adj @ msk ----------------
    for (int ch = 0; ch < NCH; ++ch) {
        const int buf = ch & 1;

        // stage adj chunk (transposed) into buf
        #pragma unroll 4
        for (int j = 0; j < BK / 4; ++j) {
            float4 v = *reinterpret_cast<const float4*>(adjp + ch * BK + j * 4);
            S.u.adjt[buf][kL][j * 4 + 0][mL] = v.x;
            S.u.adjt[buf][kL][j * 4 + 1][mL] = v.y;
            S.u.adjt[buf][kL][j * 4 + 2][mL] = v.z;
            S.u.adjt[buf][kL][j * 4 + 3][mL] = v.w;
        }
        // stage masked, duplicated g chunk into buf
        #pragma unroll
        for (int r = 0; r < BK / 8; ++r) {
            int nn = ng + r * 8;
            int n  = ch * BK + nn;
            float mv = lo32(S.mskd[n]);
            float v  = fcb[(size_t)n * Dd * Tt];
            S.gd[buf][nn][dl] = dup2(mv * v);
        }
        __syncthreads();   // single barrier: safe with double buffering

        #pragma unroll 4
        for (int nn = 0; nn < BK; ++nn) {
            const u64* arow = reinterpret_cast<const u64*>(&S.u.adjt[buf][kk][nn][mg * 8]);
            const ulonglong2 a01 = *reinterpret_cast<const ulonglong2*>(arow);
            const ulonglong2 a23 = *reinterpret_cast<const ulonglong2*>(arow + 2);
            const u64* grow = &S.gd[buf][nn][dg * 4];
            const ulonglong2 g01 = *reinterpret_cast<const ulonglong2*>(grow);
            const ulonglong2 g23 = *reinterpret_cast<const ulonglong2*>(grow + 2);
            const u64 mm = S.mskd[ch * BK + nn];
            const u64 ap[4] = {a01.x, a01.y, a23.x, a23.y};
            const u64 gp[4] = {g01.x, g01.y, g23.x, g23.y};
            #pragma unroll
            for (int mp = 0; mp < 4; ++mp) {
                ffma2(acc[mp][0], ap[mp], gp[0]);
                ffma2(acc[mp][1], ap[mp], gp[1]);
                ffma2(acc[mp][2], ap[mp], gp[2]);
                ffma2(acc[mp][3], ap[mp], gp[3]);
                ffma2(dacc[mp],   ap[mp], mm);
            }
        }
    }

    __syncthreads();   // all adjt reads done before agg overwrites the union

    // ---------------- epilogue: agg = ft + raw/(denom+1) ----------------
    {
        const float* ftb = ft + (size_t)((b * Mm + mt * BM) * Dd) * Tt + t;
        #pragma unroll
        for (int mp = 0; mp < 4; ++mp) {
            const float dv[2] = {lo32(dacc[mp]), hi32(dacc[mp])};
            #pragma unroll
            for (int p = 0; p < 2; ++p) {
                const int m = mg * 8 + mp * 2 + p;
                const float inv = 1.0f / (dv[p] + 1.0f);
                const float* fr = ftb + (size_t)(m * Dd + dg * 4) * Tt;
                const float f0 = fr[0];
                const float f1 = fr[Tt];
                const float f2 = fr[2 * Tt];
                const float f3 = fr[3 * Tt];
                float4 ag;
                ag.x = fmaf(p ? hi32(acc[mp][0]) : lo32(acc[mp][0]), inv, f0);
                ag.y = fmaf(p ? hi32(acc[mp][1]) : lo32(acc[mp][1]), inv, f1);
                ag.z = fmaf(p ? hi32(acc[mp][2]) : lo32(acc[mp][2]), inv, f2);
                ag.w = fmaf(p ? hi32(acc[mp][3]) : lo32(acc[mp][3]), inv, f3);
                *reinterpret_cast<float4*>(&S.u.agg[m][Dd + kk * Dd + dg * 4]) = ag;
                if (kk == 0) {
                    *reinterpret_cast<float4*>(&S.u.agg[m][dg * 4]) = make_float4(f0, f1, f2, f3);
                }
            }
        }
    }
    __syncthreads();

    // ---------------- MLP: y[m][o] = relu(bias + agg . W) ----------------
    const int og  = tid & 15;
    const int mg2 = tid >> 4;
    float4 y[8];
    #pragma unroll
    for (int i = 0; i < 8; ++i) y[i] = make_float4(0.f, 0.f, 0.f, 0.f);

    #pragma unroll 4
    for (int c = 0; c < CC; c += 4) {
        const float4 w0 = *reinterpret_cast<const float4*>(&S.Wt[c + 0][og * 4]);
        const float4 w1 = *reinterpret_cast<const float4*>(&S.Wt[c + 1][og * 4]);
        const float4 w2 = *reinterpret_cast<const float4*>(&S.Wt[c + 2][og * 4]);
        const float4 w3 = *reinterpret_cast<const float4*>(&S.Wt[c + 3][og * 4]);
        #pragma unroll
        for (int i = 0; i < 8; ++i) {
            const float4 a = *reinterpret_cast<const float4*>(&S.u.agg[mg2 * 8 + i][c]);
            y[i].x = fmaf(a.x, w0.x, fmaf(a.y, w1.x, fmaf(a.z, w2.x, fmaf(a.w, w3.x, y[i].x))));
            y[i].y = fmaf(a.x, w0.y, fmaf(a.y, w1.y, fmaf(a.z, w2.y, fmaf(a.w, w3.y, y[i].y))));
            y[i].z = fmaf(a.x, w0.z, fmaf(a.y, w1.z, fmaf(a.z, w2.z, fmaf(a.w, w3.z, y[i].z))));
            y[i].w = fmaf(a.x, w0.w, fmaf(a.y, w1.w, fmaf(a.z, w2.w, fmaf(a.w, w3.w, y[i].w))));
        }
    }

    const float bx = bm[og * 4 + 0];
    const float by = bm[og * 4 + 1];
    const float bz = bm[og * 4 + 2];
    const float bw = bm[og * 4 + 3];
    float* ob = out + (size_t)((b * Mm + mt * BM) * CO) * Tt + t;
    #pragma unroll
    for (int i = 0; i < 8; ++i) {
        const int m = mg2 * 8 + i;
        float* op = ob + (size_t)(m * CO + og * 4) * Tt;
        op[0]      = fmaxf(y[i].x + bx, 0.f);
        op[Tt]     = fmaxf(y[i].y + by, 0.f);
        op[2 * Tt] = fmaxf(y[i].z + bz, 0.f);
        op[3 * Tt] = fmaxf(y[i].w + bw, 0.f);
    }
}

} // namespace

extern "C" void kernel_launch(void* const* d_in, const int* in_sizes, int n_in,
                              void* d_out, int out_size) {
    const float* fc   = (const float*)d_in[0];
    const float* ft   = (const float*)d_in[1];
    const float* adj  = (const float*)d_in[2];
    const float* mask = (const float*)d_in[3];
    const float* Wm   = (const float*)d_in[4];
    const float* bm   = (const float*)d_in[5];
    float* out = (float*)d_out;

    cudaFuncSetAttribute(graph_agg_kernel,
                         cudaFuncAttributeMaxDynamicSharedMemorySize, SMEM_BYTES);
    dim3 grid(Tt, Mm / BM, Bb);
    graph_agg_kernel<<<grid, BDIM, SMEM_BYTES>>>(fc, ft, adj, mask, Wm, bm, out);
}

// round 9
// speedup vs baseline: 1.3737x; 1.3737x over previous
#include <cuda_runtime.h>

namespace {

constexpr int Bb  = 2;
constexpr int Nn  = 512;
constexpr int Mm  = 256;
constexpr int Dd  = 32;
constexpr int Tt  = 128;
constexpr int ORD = 2;
constexpr int CC  = 96;   // (ORD+1)*Dd
constexpr int CO  = 64;

constexpr int BM   = 128;
constexpr int BK   = 16;        // n-chunk (prefetch fits registers)
constexpr int BDIM = 256;
constexpr int NCH  = Nn / BK;   // 32

typedef unsigned long long u64;

struct Smem {
    union {
        float adjt[2][ORD][BK][BM];   // 32 KB double-buffered
        float agg[BM][CC];            // 48 KB epilogue/MLP
    } u;
    float gch[2][BK][Dd];             // per-chunk masked g: 4 KB (NO duplication)
    u64   mskd[Nn];                   // (1-mask,1-mask) pairs: 4 KB
    float Wt[CC][CO];                 // 24 KB
};
constexpr int SMEM_BYTES = (int)sizeof(Smem);  // ~80 KB -> 2 CTAs/SM

__device__ __forceinline__ void ffma2(u64& d, u64 a, u64 b) {
    asm("fma.rn.f32x2 %0, %1, %2, %0;" : "+l"(d) : "l"(a), "l"(b));
}
__device__ __forceinline__ u64 dup2(float v) {
    u64 r; asm("mov.b64 %0, {%1, %1};" : "=l"(r) : "f"(v)); return r;
}
__device__ __forceinline__ float lo32(u64 v) { return __uint_as_float((unsigned)v); }
__device__ __forceinline__ float hi32(u64 v) { return __uint_as_float((unsigned)(v >> 32)); }

__global__ void __launch_bounds__(BDIM, 2)
graph_agg_kernel(const float* __restrict__ fc,    // [B,N,D,T]
                 const float* __restrict__ ft,    // [B,M,D,T]
                 const float* __restrict__ adj,   // [B,ORD,M,N]
                 const float* __restrict__ mask,  // [B,T,N]
                 const float* __restrict__ Wm,    // [CO,CC]
                 const float* __restrict__ bm,    // [CO]
                 float* __restrict__ out)         // [B,M,CO,T]
{
    extern __shared__ char smraw[];
    Smem& S = *reinterpret_cast<Smem*>(smraw);

    const int t   = blockIdx.x;
    const int mt  = blockIdx.y;
    const int b   = blockIdx.z;
    const int tid = threadIdx.x;

    // ---------------- prologue: Wt, mskd ----------------
    for (int i = tid; i < CO * CC; i += BDIM) {
        int o = i / CC, c = i % CC;
        S.Wt[c][o] = Wm[i];
    }
    {
        const float* maskp = mask + (b * Tt + t) * Nn;
        #pragma unroll
        for (int r = 0; r < Nn / BDIM; ++r) {
            int n = tid + r * BDIM;
            S.mskd[n] = dup2(1.0f - maskp[n]);
        }
    }
    __syncthreads();

    // compute roles
    const int kk = tid >> 7;          // order 0/1
    const int mg = (tid >> 3) & 15;   // 8 m's = 4 m-pairs
    const int dg = tid & 7;           // 4 d's

    // loader roles
    const int kL = tid >> 7;
    const int mL = tid & 127;
    const float* adjp = adj + (size_t)((b * ORD + kL) * Mm + mt * BM + mL) * Nn;
    const int dl = tid & 31;          // d lane for g producer
    const int ng = tid >> 5;          // 8 groups, 2 rows each (BK=16)
    const float* fcb = fc + ((size_t)(b * Nn) * Dd + dl) * Tt + t;

    u64 acc[4][4];                    // [m-pair][d]: (m_even, m_odd)
    u64 dacc[4];
    #pragma unroll
    for (int i = 0; i < 4; ++i) {
        dacc[i] = 0ull;
        #pragma unroll
        for (int j = 0; j < 4; ++j) acc[i][j] = 0ull;
    }

    // register prefetch buffers (chunk ch+1)
    float4 pa[BK / 4];                // 16 adj floats
    float  pg[2];                     // 2 g floats

    // preload chunk 0
    #pragma unroll
    for (int j = 0; j < BK / 4; ++j)
        pa[j] = *reinterpret_cast<const float4*>(adjp + j * 4);
    #pragma unroll
    for (int r = 0; r < 2; ++r)
        pg[r] = fcb[(size_t)(ng + r * 8) * Dd * Tt];

    // ---------------- main loop ----------------
    for (int ch = 0; ch < NCH; ++ch) {
        const int buf = ch & 1;

        // stage prefetched chunk into smem
        #pragma unroll
        for (int j = 0; j < BK / 4; ++j) {
            S.u.adjt[buf][kL][j * 4 + 0][mL] = pa[j].x;
            S.u.adjt[buf][kL][j * 4 + 1][mL] = pa[j].y;
            S.u.adjt[buf][kL][j * 4 + 2][mL] = pa[j].z;
            S.u.adjt[buf][kL][j * 4 + 3][mL] = pa[j].w;
        }
        #pragma unroll
        for (int r = 0; r < 2; ++r) {
            int nn = ng + r * 8;
            int n  = ch * BK + nn;
            S.gch[buf][nn][dl] = lo32(S.mskd[n]) * pg[r];
        }

        // issue LDG for next chunk (hidden behind this chunk's compute)
        if (ch + 1 < NCH) {
            #pragma unroll
            for (int j = 0; j < BK / 4; ++j)
                pa[j] = *reinterpret_cast<const float4*>(adjp + (ch + 1) * BK + j * 4);
            #pragma unroll
            for (int r = 0; r < 2; ++r)
                pg[r] = fcb[(size_t)((ch + 1) * BK + ng + r * 8) * Dd * Tt];
        }

        __syncthreads();   // single barrier; double buffer makes it safe

        #pragma unroll 8
        for (int nn = 0; nn < BK; ++nn) {
            const u64* arow = reinterpret_cast<const u64*>(&S.u.adjt[buf][kk][nn][mg * 8]);
            const ulonglong2 a01 = *reinterpret_cast<const ulonglong2*>(arow);
            const ulonglong2 a23 = *reinterpret_cast<const ulonglong2*>(arow + 2);
            const float4 gv = *reinterpret_cast<const float4*>(&S.gch[buf][nn][dg * 4]);
            const u64 mm = S.mskd[ch * BK + nn];
            const u64 g0 = dup2(gv.x), g1 = dup2(gv.y), g2 = dup2(gv.z), g3 = dup2(gv.w);
            const u64 ap[4] = {a01.x, a01.y, a23.x, a23.y};
            #pragma unroll
            for (int mp = 0; mp < 4; ++mp) {
                ffma2(acc[mp][0], ap[mp], g0);
                ffma2(acc[mp][1], ap[mp], g1);
                ffma2(acc[mp][2], ap[mp], g2);
                ffma2(acc[mp][3], ap[mp], g3);
                ffma2(dacc[mp],   ap[mp], mm);
            }
        }
    }

    __syncthreads();   // all adjt reads done before agg overwrites the union

    // ---------------- epilogue: agg = ft + raw/(denom+1) ----------------
    {
        const float* ftb = ft + (size_t)((b * Mm + mt * BM) * Dd) * Tt + t;
        #pragma unroll
        for (int mp = 0; mp < 4; ++mp) {
            const float dv[2] = {lo32(dacc[mp]), hi32(dacc[mp])};
            #pragma unroll
            for (int p = 0; p < 2; ++p) {
                const int m = mg * 8 + mp * 2 + p;
                const float inv = 1.0f / (dv[p] + 1.0f);
                const float* fr = ftb + (size_t)(m * Dd + dg * 4) * Tt;
                const float f0 = fr[0];
                const float f1 = fr[Tt];
                const float f2 = fr[2 * Tt];
                const float f3 = fr[3 * Tt];
                float4 ag;
                ag.x = fmaf(p ? hi32(acc[mp][0]) : lo32(acc[mp][0]), inv, f0);
                ag.y = fmaf(p ? hi32(acc[mp][1]) : lo32(acc[mp][1]), inv, f1);
                ag.z = fmaf(p ? hi32(acc[mp][2]) : lo32(acc[mp][2]), inv, f2);
                ag.w = fmaf(p ? hi32(acc[mp][3]) : lo32(acc[mp][3]), inv, f3);
                *reinterpret_cast<float4*>(&S.u.agg[m][Dd + kk * Dd + dg * 4]) = ag;
                if (kk == 0) {
                    *reinterpret_cast<float4*>(&S.u.agg[m][dg * 4]) = make_float4(f0, f1, f2, f3);
                }
            }
        }
    }
    __syncthreads();

    // ---------------- MLP: y[m][o] = relu(bias + agg . W) ----------------
    const int og  = tid & 15;
    const int mg2 = tid >> 4;
    float4 y[8];
    #pragma unroll
    for (int i = 0; i < 8; ++i) y[i] = make_float4(0.f, 0.f, 0.f, 0.f);

    #pragma unroll 4
    for (int c = 0; c < CC; c += 4) {
        const float4 w0 = *reinterpret_cast<const float4*>(&S.Wt[c + 0][og * 4]);
        const float4 w1 = *reinterpret_cast<const float4*>(&S.Wt[c + 1][og * 4]);
        const float4 w2 = *reinterpret_cast<const float4*>(&S.Wt[c + 2][og * 4]);
        const float4 w3 = *reinterpret_cast<const float4*>(&S.Wt[c + 3][og * 4]);
        #pragma unroll
        for (int i = 0; i < 8; ++i) {
            const float4 a = *reinterpret_cast<const float4*>(&S.u.agg[mg2 * 8 + i][c]);
            y[i].x = fmaf(a.x, w0.x, fmaf(a.y, w1.x, fmaf(a.z, w2.x, fmaf(a.w, w3.x, y[i].x))));
            y[i].y = fmaf(a.x, w0.y, fmaf(a.y, w1.y, fmaf(a.z, w2.y, fmaf(a.w, w3.y, y[i].y))));
            y[i].z = fmaf(a.x, w0.z, fmaf(a.y, w1.z, fmaf(a.z, w2.z, fmaf(a.w, w3.z, y[i].z))));
            y[i].w = fmaf(a.x, w0.w, fmaf(a.y, w1.w, fmaf(a.z, w2.w, fmaf(a.w, w3.w, y[i].w))));
        }
    }

    const float bx = bm[og * 4 + 0];
    const float by = bm[og * 4 + 1];
    const float bz = bm[og * 4 + 2];
    const float bw = bm[og * 4 + 3];
    float* ob = out + (size_t)((b * Mm + mt * BM) * CO) * Tt + t;
    #pragma unroll
    for (int i = 0; i < 8; ++i) {
        const int m = mg2 * 8 + i;
        float* op = ob + (size_t)(m * CO + og * 4) * Tt;
        op[0]      = fmaxf(y[i].x + bx, 0.f);
        op[Tt]     = fmaxf(y[i].y + by, 0.f);
        op[2 * Tt] = fmaxf(y[i].z + bz, 0.f);
        op[3 * Tt] = fmaxf(y[i].w + bw, 0.f);
    }
}

} // namespace

extern "C" void kernel_launch(void* const* d_in, const int* in_sizes, int n_in,
                              void* d_out, int out_size) {
    const float* fc   = (const float*)d_in[0];
    const float* ft   = (const float*)d_in[1];
    const float* adj  = (const float*)d_in[2];
    const float* mask = (const float*)d_in[3];
    const float* Wm   = (const float*)d_in[4];
    const float* bm   = (const float*)d_in[5];
    float* out = (float*)d_out;

    cudaFuncSetAttribute(graph_agg_kernel,
                         cudaFuncAttributeMaxDynamicSharedMemorySize, SMEM_BYTES);
    dim3 grid(Tt, Mm / BM, Bb);
    graph_agg_kernel<<<grid, BDIM, SMEM_BYTES>>>(fc, ft, adj, mask, Wm, bm, out);
}

// round 11
// speedup vs baseline: 2.7188x; 1.9791x over previous
#include <cuda_runtime.h>
#include <cuda_bf16.h>

namespace {

typedef unsigned int  u32;
typedef unsigned long long u64;

constexpr int Bb  = 2;
constexpr int Nn  = 512;   // context nodes = GEMM K
constexpr int Mm  = 256;
constexpr int Dd  = 32;
constexpr int Tt  = 128;
constexpr int ORD = 2;
constexpr int CO  = 64;

constexpr int RR  = ORD * Mm;          // 512 GEMM rows per b: r = k*256+m
constexpr int NC  = (Dd + 1) * Tt;     // 4224 GEMM cols per b: c = d*128+t, d=32 -> denom plane

// ---------------- scratch (device globals; allocation-free) ----------------
__device__ __nv_bfloat16 d_Ah[Bb * RR * Nn];      // 1 MB
__device__ __nv_bfloat16 d_Al[Bb * RR * Nn];
__device__ __nv_bfloat16 d_Gh[(size_t)Bb * NC * Nn];  // 8.65 MB
__device__ __nv_bfloat16 d_Gl[(size_t)Bb * NC * Nn];
__device__ float         d_Cb[(size_t)Bb * RR * NC];  // 17.3 MB

__device__ __forceinline__ void bsplit(float v, __nv_bfloat16& h, __nv_bfloat16& l) {
    h = __float2bfloat16(v);
    l = __float2bfloat16(v - __bfloat162float(h));
}
__device__ __forceinline__ void ffma2(u64& d, u64 a, u64 b) {
    asm("fma.rn.f32x2 %0, %1, %2, %0;" : "+l"(d) : "l"(a), "l"(b));
}
__device__ __forceinline__ u64 dup2(float v) {
    u64 r; asm("mov.b64 %0, {%1, %1};" : "=l"(r) : "f"(v)); return r;
}
__device__ __forceinline__ float lo32(u64 v) { return __uint_as_float((u32)v); }
__device__ __forceinline__ float hi32(u64 v) { return __uint_as_float((u32)(v >> 32)); }

__device__ __forceinline__ void mma16816(float* c, const u32* a, const u32* b) {
    asm volatile(
        "mma.sync.aligned.m16n8k16.row.col.f32.bf16.bf16.f32 "
        "{%0,%1,%2,%3}, {%4,%5,%6,%7}, {%8,%9}, {%0,%1,%2,%3};\n"
        : "+f"(c[0]), "+f"(c[1]), "+f"(c[2]), "+f"(c[3])
        : "r"(a[0]), "r"(a[1]), "r"(a[2]), "r"(a[3]), "r"(b[0]), "r"(b[1]));
}

// ================= kernel A: split adj -> bf16 hi/lo =================
__global__ void __launch_bounds__(256)
k_split_adj(const float* __restrict__ adj) {
    int i4 = blockIdx.x * 256 + threadIdx.x;           // 131072 float4's
    float4 v = reinterpret_cast<const float4*>(adj)[i4];
    __nv_bfloat16 h0, l0, h1, l1, h2, l2, h3, l3;
    bsplit(v.x, h0, l0); bsplit(v.y, h1, l1);
    bsplit(v.z, h2, l2); bsplit(v.w, h3, l3);
    int o = i4 * 4;
    *reinterpret_cast<__nv_bfloat162*>(&d_Ah[o])     = __nv_bfloat162(h0, h1);
    *reinterpret_cast<__nv_bfloat162*>(&d_Ah[o + 2]) = __nv_bfloat162(h2, h3);
    *reinterpret_cast<__nv_bfloat162*>(&d_Al[o])     = __nv_bfloat162(l0, l1);
    *reinterpret_cast<__nv_bfloat162*>(&d_Al[o + 2]) = __nv_bfloat162(l2, l3);
}

// ================= kernel B: build G^T (hi/lo) =================
// G[c=(dd*128+t)][n] = z[t,n] * fc[b,n,dd,t]   (dd<32)
// G[4096+t][n]      = z[t,n]                    (denom plane)
struct SB {
    float ftile[64][132];   // [n'][t]
    float ztile[128][69];   // [t][n']
};
__global__ void __launch_bounds__(256)
k_build_G(const float* __restrict__ fc, const float* __restrict__ mask) {
    extern __shared__ char raw[];
    SB& S = *reinterpret_cast<SB*>(raw);
    const int dd = blockIdx.x;       // 0..32
    const int nb = blockIdx.y;       // 0..7  (64 n each)
    const int b  = blockIdx.z;
    const int tid = threadIdx.x;

    {   // z tile: rows t, 64 n
        int t = tid >> 1, h = tid & 1;
        const float4* mp = reinterpret_cast<const float4*>(
            &mask[(size_t)(b * Tt + t) * Nn + nb * 64 + h * 32]);
        #pragma unroll
        for (int i = 0; i < 8; ++i) {
            float4 v = mp[i];
            S.ztile[t][h * 32 + i * 4 + 0] = 1.0f - v.x;
            S.ztile[t][h * 32 + i * 4 + 1] = 1.0f - v.y;
            S.ztile[t][h * 32 + i * 4 + 2] = 1.0f - v.z;
            S.ztile[t][h * 32 + i * 4 + 3] = 1.0f - v.w;
        }
    }
    if (dd < Dd) {  // fc tile: rows n' (64), 128 t
        int r = tid >> 2, q = tid & 3;
        const float4* fp = reinterpret_cast<const float4*>(
            &fc[((size_t)(b * Nn + nb * 64 + r) * Dd + dd) * Tt + q * 32]);
        #pragma unroll
        for (int i = 0; i < 8; ++i) {
            float4 v = fp[i];
            S.ftile[r][q * 32 + i * 4 + 0] = v.x;
            S.ftile[r][q * 32 + i * 4 + 1] = v.y;
            S.ftile[r][q * 32 + i * 4 + 2] = v.z;
            S.ftile[r][q * 32 + i * 4 + 3] = v.w;
        }
    }
    __syncthreads();

    const int t = tid & 127, h = tid >> 7;
    const int c = (dd < Dd) ? dd * Tt + t : Dd * Tt + t;
    const size_t obase = ((size_t)b * NC + c) * Nn + nb * 64 + h * 32;
    #pragma unroll
    for (int j = 0; j < 32; j += 2) {
        int n0 = h * 32 + j;
        float z0 = S.ztile[t][n0], z1 = S.ztile[t][n0 + 1];
        float v0 = (dd < Dd ? S.ftile[n0][t]     : 1.0f) * z0;
        float v1 = (dd < Dd ? S.ftile[n0 + 1][t] : 1.0f) * z1;
        __nv_bfloat16 h0, l0, h1, l1;
        bsplit(v0, h0, l0); bsplit(v1, h1, l1);
        *reinterpret_cast<__nv_bfloat162*>(&d_Gh[obase + j]) = __nv_bfloat162(h0, h1);
        *reinterpret_cast<__nv_bfloat162*>(&d_Gl[obase + j]) = __nv_bfloat162(l0, l1);
    }
}

// ================= kernel C: HMMA GEMM =================
// C[b][r][c] = sum_n (Ah+Al)[r][n] * (Gh+Gl)[c][n]  (drop lo*lo)
constexpr int BKk = 64;
constexpr int LDK = 72;     // padded smem row (bf16): conflict-free frag loads
struct SC {
    __nv_bfloat16 Ah[128][LDK];
    __nv_bfloat16 Al[128][LDK];
    __nv_bfloat16 Bh[128][LDK];
    __nv_bfloat16 Bl[128][LDK];
};
__global__ void __launch_bounds__(256)
k_gemm(void) {
    extern __shared__ char raw[];
    SC& S = *reinterpret_cast<SC*>(raw);
    const int nt = blockIdx.x;   // 0..32
    const int mt = blockIdx.y;   // 0..3
    const int b  = blockIdx.z;
    const int tid = threadIdx.x;
    const int w   = tid >> 5;
    const int lane = tid & 31;
    const int g  = lane >> 2;
    const int tg = lane & 3;
    const int wm = w & 1;        // 2 M-warps (64 rows each)
    const int wn = w >> 1;       // 4 N-warps (32 cols each)

    float acc[4][4][4];
    #pragma unroll
    for (int i = 0; i < 4; ++i)
        #pragma unroll
        for (int j = 0; j < 4; ++j)
            #pragma unroll
            for (int q = 0; q < 4; ++q) acc[i][j][q] = 0.0f;

    const int r  = tid >> 1;     // loader row 0..127
    const int hh = tid & 1;
    const size_t aRow = (size_t)(b * RR + mt * 128 + r) * Nn;
    const size_t bRow = ((size_t)b * NC + nt * 128 + r) * Nn;

    for (int kc = 0; kc < Nn / BKk; ++kc) {
        const int kof = kc * BKk + hh * 32;
        {
            const uint4* sa = reinterpret_cast<const uint4*>(&d_Ah[aRow + kof]);
            const uint4* sl = reinterpret_cast<const uint4*>(&d_Al[aRow + kof]);
            const uint4* gb = reinterpret_cast<const uint4*>(&d_Gh[bRow + kof]);
            const uint4* gl = reinterpret_cast<const uint4*>(&d_Gl[bRow + kof]);
            #pragma unroll
            for (int q = 0; q < 4; ++q) {
                *reinterpret_cast<uint4*>(&S.Ah[r][hh * 32 + q * 8]) = sa[q];
                *reinterpret_cast<uint4*>(&S.Al[r][hh * 32 + q * 8]) = sl[q];
                *reinterpret_cast<uint4*>(&S.Bh[r][hh * 32 + q * 8]) = gb[q];
                *reinterpret_cast<uint4*>(&S.Bl[r][hh * 32 + q * 8]) = gl[q];
            }
        }
        __syncthreads();

        #pragma unroll
        for (int ks = 0; ks < BKk / 16; ++ks) {
            const int ck = ks * 16;
            u32 ah[4][4], bh[4][2], bl[4][2];
            #pragma unroll
            for (int i = 0; i < 4; ++i) {
                int m0 = wm * 64 + i * 16;
                ah[i][0] = *reinterpret_cast<const u32*>(&S.Ah[m0 + g    ][ck + 2 * tg]);
                ah[i][1] = *reinterpret_cast<const u32*>(&S.Ah[m0 + 8 + g][ck + 2 * tg]);
                ah[i][2] = *reinterpret_cast<const u32*>(&S.Ah[m0 + g    ][ck + 8 + 2 * tg]);
                ah[i][3] = *reinterpret_cast<const u32*>(&S.Ah[m0 + 8 + g][ck + 8 + 2 * tg]);
            }
            #pragma unroll
            for (int j = 0; j < 4; ++j) {
                int n0 = wn * 32 + j * 8 + g;
                bh[j][0] = *reinterpret_cast<const u32*>(&S.Bh[n0][ck + 2 * tg]);
                bh[j][1] = *reinterpret_cast<const u32*>(&S.Bh[n0][ck + 8 + 2 * tg]);
                bl[j][0] = *reinterpret_cast<const u32*>(&S.Bl[n0][ck + 2 * tg]);
                bl[j][1] = *reinterpret_cast<const u32*>(&S.Bl[n0][ck + 8 + 2 * tg]);
            }
            #pragma unroll
            for (int i = 0; i < 4; ++i)
                #pragma unroll
                for (int j = 0; j < 4; ++j) {
                    mma16816(acc[i][j], ah[i], bh[j]);   // hi*hi
                    mma16816(acc[i][j], ah[i], bl[j]);   // hi*lo
                }
            u32 al[4][4];
            #pragma unroll
            for (int i = 0; i < 4; ++i) {
                int m0 = wm * 64 + i * 16;
                al[i][0] = *reinterpret_cast<const u32*>(&S.Al[m0 + g    ][ck + 2 * tg]);
                al[i][1] = *reinterpret_cast<const u32*>(&S.Al[m0 + 8 + g][ck + 2 * tg]);
                al[i][2] = *reinterpret_cast<const u32*>(&S.Al[m0 + g    ][ck + 8 + 2 * tg]);
                al[i][3] = *reinterpret_cast<const u32*>(&S.Al[m0 + 8 + g][ck + 8 + 2 * tg]);
            }
            #pragma unroll
            for (int i = 0; i < 4; ++i)
                #pragma unroll
                for (int j = 0; j < 4; ++j)
                    mma16816(acc[i][j], al[i], bh[j]);   // lo*hi
        }
        __syncthreads();
    }

    // epilogue: write raw C
    #pragma unroll
    for (int i = 0; i < 4; ++i) {
        const int r0 = mt * 128 + wm * 64 + i * 16 + g;
        #pragma unroll
        for (int j = 0; j < 4; ++j) {
            const int col = nt * 128 + wn * 32 + j * 8 + 2 * tg;
            float* p0 = &d_Cb[((size_t)(b * RR) + r0) * NC + col];
            *reinterpret_cast<float2*>(p0)            = make_float2(acc[i][j][0], acc[i][j][1]);
            *reinterpret_cast<float2*>(p0 + 8 * NC)   = make_float2(acc[i][j][2], acc[i][j][3]);
        }
    }
}

// ================= kernel D: epilogue + MLP =================
struct SD {
    union {
        float agg[96][132];     // channels x t
        float ysm[64][133];     // outputs x t
    } u;
    u64 Wp[96][32];             // (W[2o],W[2o+1]) pairs per channel
};
__global__ void __launch_bounds__(128)
k_epi(const float* __restrict__ ft, const float* __restrict__ Wm,
      const float* __restrict__ bm, float* __restrict__ out) {
    extern __shared__ char raw[];
    SD& S = *reinterpret_cast<SD*>(raw);
    const int m = blockIdx.x;
    const int b = blockIdx.y;
    const int tid = threadIdx.x;   // = t

    // W pairs: Wp[c][op] = (W[2op][c], W[2op+1][c])
    for (int idx = tid; idx < 96 * 32; idx += 128) {
        int c = idx >> 5, op = idx & 31;
        u32 w0 = __float_as_uint(Wm[(2 * op) * 96 + c]);
        u32 w1 = __float_as_uint(Wm[(2 * op + 1) * 96 + c]);
        S.Wp[c][op] = ((u64)w1 << 32) | (u64)w0;
    }

    // step 1: assemble agg channels
    {
        const size_t r0 = (size_t)(b * RR + m) * NC;          // k=0 row
        const size_t r1 = (size_t)(b * RR + Mm + m) * NC;     // k=1 row
        const float iv0 = 1.0f / (d_Cb[r0 + Dd * Tt + tid] + 1.0f);
        const float iv1 = 1.0f / (d_Cb[r1 + Dd * Tt + tid] + 1.0f);
        const float* ftb = &ft[(size_t)((b * Mm + m) * Dd) * Tt + tid];
        #pragma unroll 8
        for (int d = 0; d < Dd; ++d) {
            float ftv = ftb[(size_t)d * Tt];
            S.u.agg[d][tid]      = ftv;
            S.u.agg[Dd + d][tid] = fmaf(d_Cb[r0 + d * Tt + tid], iv0, ftv);
            S.u.agg[2 * Dd + d][tid] = fmaf(d_Cb[r1 + d * Tt + tid], iv1, ftv);
        }
    }
    __syncthreads();

    // step 2: MLP — warp w handles t in [32w,32w+32); lane = o-pair
    const int w = tid >> 5, l = tid & 31;
    const int tb = 32 * w;
    u64 acc[32];
    #pragma unroll
    for (int i = 0; i < 32; ++i) acc[i] = 0ull;

    for (int c = 0; c < 96; ++c) {
        const u64 wv = S.Wp[c][l];
        #pragma unroll
        for (int q = 0; q < 8; ++q) {
            float4 av = *reinterpret_cast<const float4*>(&S.u.agg[c][tb + q * 4]);
            ffma2(acc[q * 4 + 0], wv, dup2(av.x));
            ffma2(acc[q * 4 + 1], wv, dup2(av.y));
            ffma2(acc[q * 4 + 2], wv, dup2(av.z));
            ffma2(acc[q * 4 + 3], wv, dup2(av.w));
        }
    }
    __syncthreads();   // agg reads done before ysm overwrites the union

    {
        const float2 bias = *reinterpret_cast<const float2*>(&bm[2 * l]);
        #pragma unroll
        for (int tt = 0; tt < 32; ++tt) {
            S.u.ysm[2 * l][tb + tt]     = fmaxf(lo32(acc[tt]) + bias.x, 0.0f);
            S.u.ysm[2 * l + 1][tb + tt] = fmaxf(hi32(acc[tt]) + bias.y, 0.0f);
        }
    }
    __syncthreads();

    float* ob = &out[(size_t)((b * Mm + m) * CO) * Tt + tid];
    #pragma unroll 8
    for (int o = 0; o < CO; ++o)
        ob[(size_t)o * Tt] = S.u.ysm[o][tid];
}

} // namespace

extern "C" void kernel_launch(void* const* d_in, const int* in_sizes, int n_in,
                              void* d_out, int out_size) {
    const float* fc   = (const float*)d_in[0];  // [2,512,32,128]
    const float* ft   = (const float*)d_in[1];  // [2,256,32,128]
    const float* adj  = (const float*)d_in[2];  // [2,2,256,512]
    const float* mask = (const float*)d_in[3];  // [2,128,512]
    const float* Wm   = (const float*)d_in[4];  // [64,96]
    const float* bm   = (const float*)d_in[5];  // [64]
    float* out = (float*)d_out;                 // [2,256,64,128]

    static bool init = false;
    if (!init) {
        cudaFuncSetAttribute(k_build_G, cudaFuncAttributeMaxDynamicSharedMemorySize, (int)sizeof(SB));
        cudaFuncSetAttribute(k_gemm,    cudaFuncAttributeMaxDynamicSharedMemorySize, (int)sizeof(SC));
        cudaFuncSetAttribute(k_epi,     cudaFuncAttributeMaxDynamicSharedMemorySize, (int)sizeof(SD));
        init = true;
    }

    k_split_adj<<<512, 256>>>(adj);
    k_build_G<<<dim3(Dd + 1, 8, Bb), 256, sizeof(SB)>>>(fc, mask);
    k_gemm<<<dim3(NC / 128, RR / 128, Bb), 256, sizeof(SC)>>>();
    k_epi<<<dim3(Mm, Bb), 128, sizeof(SD)>>>(ft, Wm, bm, out);
}